// round 1
// baseline (speedup 1.0000x reference)
#include <cuda_runtime.h>
#include <cuda_bf16.h>
#include <cstdint>

// ---------------- constants (shapes fixed by problem) ----------------
#define MAX_N 100000
#define D     128           // feature dim (in and hidden)

// ---------------- static device scratch (no allocations allowed) ----------------
__device__ float g_deg [MAX_N];
__device__ float g_dinv[MAX_N];
__device__ float g_G  [(size_t)MAX_N * D];   // g = (h@W)*dinv
__device__ float g_ACC[(size_t)MAX_N * D];   // accumulator (init = self-loop term)
__device__ float g_H  [(size_t)MAX_N * D];   // layer activations

// ---------------- degree / dinv ----------------
__global__ void k_init_deg(float* deg, int N) {
    int i = blockIdx.x * blockDim.x + threadIdx.x;
    if (i < N) deg[i] = 1.0f;   // self-loop
}

__global__ void k_deg_accum(float* deg, const int* __restrict__ dst, int E) {
    int e = blockIdx.x * blockDim.x + threadIdx.x;
    if (e < E) atomicAdd(&deg[dst[e]], 1.0f);
}

__global__ void k_dinv(const float* __restrict__ deg, float* __restrict__ dinv, int N) {
    int i = blockIdx.x * blockDim.x + threadIdx.x;
    if (i < N) dinv[i] = rsqrtf(deg[i]);
}

// ---------------- fused GEMM + row scale:  G = ACC = (X @ W) * dinv[row] ----------------
// BM=64 rows per CTA, full N=K=128. 256 threads: tm = tid>>5 (8 row-groups of 8),
// tn = tid&31 (32 col-groups of 4). A-reads are warp-uniform broadcasts (no conflicts),
// B-reads are contiguous float4 (no conflicts).
#define GEMM_BM 64
#define GEMM_SMEM ((GEMM_BM + 128) * 128 * 4)   // xs 32KB + ws 64KB = 96KB

__global__ void k_gemm_scale(const float* __restrict__ X, const float* __restrict__ W,
                             const float* __restrict__ dinv,
                             float* __restrict__ G, float* __restrict__ ACC, int N) {
    extern __shared__ float sm[];
    float* xs = sm;                   // [BM][128]
    float* ws = sm + GEMM_BM * 128;   // [128][128]
    int tid  = threadIdx.x;
    int row0 = blockIdx.x * GEMM_BM;

    // stage W (128x128 fp32 = 4096 float4)
    {
        const float4* Wv = (const float4*)W;
        float4* wsv = (float4*)ws;
        #pragma unroll
        for (int i = tid; i < 128 * 32; i += 256) wsv[i] = Wv[i];
    }
    // stage X tile (BM x 32 float4), zero-pad tail rows
    {
        float4* xsv = (float4*)xs;
        for (int i = tid; i < GEMM_BM * 32; i += 256) {
            int r = i >> 5, c = i & 31;
            int gr = row0 + r;
            float4 v = make_float4(0.f, 0.f, 0.f, 0.f);
            if (gr < N) v = ((const float4*)(X + (size_t)gr * D))[c];
            xsv[i] = v;
        }
    }
    __syncthreads();

    int tn = tid & 31;
    int tm = tid >> 5;
    float acc[8][4];
    #pragma unroll
    for (int r = 0; r < 8; r++)
        #pragma unroll
        for (int j = 0; j < 4; j++) acc[r][j] = 0.f;

    #pragma unroll 8
    for (int k = 0; k < 128; k++) {
        float4 b = ((const float4*)(ws + k * 128))[tn];
        float a[8];
        #pragma unroll
        for (int r = 0; r < 8; r++) a[r] = xs[(tm * 8 + r) * 128 + k];
        #pragma unroll
        for (int r = 0; r < 8; r++) {
            acc[r][0] = fmaf(a[r], b.x, acc[r][0]);
            acc[r][1] = fmaf(a[r], b.y, acc[r][1]);
            acc[r][2] = fmaf(a[r], b.z, acc[r][2]);
            acc[r][3] = fmaf(a[r], b.w, acc[r][3]);
        }
    }

    #pragma unroll
    for (int r = 0; r < 8; r++) {
        int gr = row0 + tm * 8 + r;
        if (gr < N) {
            float dv = dinv[gr];
            float4 v = make_float4(acc[r][0] * dv, acc[r][1] * dv,
                                   acc[r][2] * dv, acc[r][3] * dv);
            ((float4*)(G   + (size_t)gr * D))[tn] = v;
            ((float4*)(ACC + (size_t)gr * D))[tn] = v;   // self-loop init
        }
    }
}

// ---------------- edge scatter:  ACC[dst] += G[src]   (vectorized L2 atomics) ----------------
__global__ void k_scatter(const float* __restrict__ G, float* __restrict__ ACC,
                          const int* __restrict__ src, const int* __restrict__ dst, int E) {
    int gtid = blockIdx.x * blockDim.x + threadIdx.x;
    int e    = gtid >> 5;
    int lane = gtid & 31;
    if (e >= E) return;
    int s = src[e];
    int d = dst[e];
    float4 v = ((const float4*)(G + (size_t)s * D))[lane];
    float* p = ACC + (size_t)d * D + lane * 4;
    asm volatile("red.global.add.v4.f32 [%0], {%1,%2,%3,%4};"
                 :: "l"(p), "f"(v.x), "f"(v.y), "f"(v.z), "f"(v.w) : "memory");
}

// ---------------- epilogue:  H = [relu](ACC * dinv + b) ----------------
template <bool RELU>
__global__ void k_post(const float* __restrict__ ACC, const float* __restrict__ dinv,
                       const float* __restrict__ b, float* __restrict__ H, int N) {
    int i = blockIdx.x * blockDim.x + threadIdx.x;   // index over N*32 float4
    if (i >= N * 32) return;
    int r = i >> 5, c = i & 31;
    float  dv = dinv[r];
    float4 v  = ((const float4*)ACC)[i];
    float4 bb = ((const float4*)b)[c];
    v.x = fmaf(v.x, dv, bb.x);
    v.y = fmaf(v.y, dv, bb.y);
    v.z = fmaf(v.z, dv, bb.z);
    v.w = fmaf(v.w, dv, bb.w);
    if (RELU) {
        v.x = fmaxf(v.x, 0.f); v.y = fmaxf(v.y, 0.f);
        v.z = fmaxf(v.z, 0.f); v.w = fmaxf(v.w, 0.f);
    }
    ((float4*)H)[i] = v;
}

// ---------------- pair dot products: warp per pair ----------------
__global__ void k_pairs(const float* __restrict__ H, const int* __restrict__ pairs,
                        float* __restrict__ out, int P) {
    int gtid = blockIdx.x * blockDim.x + threadIdx.x;
    int w    = gtid >> 5;
    int lane = gtid & 31;
    if (w >= P) return;
    int u = pairs[2 * w];
    int v = pairs[2 * w + 1];
    float4 a = ((const float4*)(H + (size_t)u * D))[lane];
    float4 b = ((const float4*)(H + (size_t)v * D))[lane];
    float s = a.x * b.x + a.y * b.y + a.z * b.z + a.w * b.w;
    #pragma unroll
    for (int o = 16; o; o >>= 1) s += __shfl_xor_sync(0xFFFFFFFFu, s, o);
    if (lane == 0) out[w] = s;
}

// ---------------- launch ----------------
static inline float* symaddr(const void* sym) {
    void* p = nullptr;
    cudaGetSymbolAddress(&p, sym);
    return (float*)p;
}

extern "C" void kernel_launch(void* const* d_in, const int* in_sizes, int n_in,
                              void* d_out, int out_size) {
    const float* x   = (const float*)d_in[0];
    const float* W1  = (const float*)d_in[1];
    const float* b1  = (const float*)d_in[2];
    const float* W2  = (const float*)d_in[3];
    const float* b2  = (const float*)d_in[4];
    const int* eidx  = (const int*)d_in[5];
    const int* pairs_pos = (const int*)d_in[6];
    const int* pairs_neg = (const int*)d_in[7];
    float* out = (float*)d_out;

    const int N = in_sizes[0] / D;
    const int E = in_sizes[5] / 2;
    const int P = in_sizes[6] / 2;
    const int* src = eidx;
    const int* dst = eidx + E;

    float* deg  = symaddr(g_deg);
    float* dinv = symaddr(g_dinv);
    float* G    = symaddr(g_G);
    float* ACC  = symaddr(g_ACC);
    float* H    = symaddr(g_H);

    cudaFuncSetAttribute(k_gemm_scale, cudaFuncAttributeMaxDynamicSharedMemorySize, GEMM_SMEM);

    const int T = 256;
    int gridN     = (N + T - 1) / T;
    int gridE     = (E + T - 1) / T;
    int gridGemm  = (N + GEMM_BM - 1) / GEMM_BM;
    int gridScat  = (int)(((long long)E * 32 + T - 1) / T);
    int gridPost  = (N * 32 + T - 1) / T;
    int gridPairs = (int)(((long long)P * 32 + T - 1) / T);

    // degree + normalization
    k_init_deg <<<gridN, T>>>(deg, N);
    k_deg_accum<<<gridE, T>>>(deg, dst, E);
    k_dinv     <<<gridN, T>>>(deg, dinv, N);

    // layer 1
    k_gemm_scale<<<gridGemm, T, GEMM_SMEM>>>(x, W1, dinv, G, ACC, N);
    k_scatter   <<<gridScat, T>>>(G, ACC, src, dst, E);
    k_post<true><<<gridPost, T>>>(ACC, dinv, b1, H, N);

    // layer 2
    k_gemm_scale<<<gridGemm, T, GEMM_SMEM>>>(H, W2, dinv, G, ACC, N);
    k_scatter   <<<gridScat, T>>>(G, ACC, src, dst, E);
    k_post<false><<<gridPost, T>>>(ACC, dinv, b2, H, N);

    // link prediction
    k_pairs<<<gridPairs, T>>>(H, pairs_pos, out,     P);
    k_pairs<<<gridPairs, T>>>(H, pairs_neg, out + P, P);
}

// round 2
// speedup vs baseline: 1.5518x; 1.5518x over previous
#include <cuda_runtime.h>
#include <cuda_bf16.h>
#include <cstdint>

#define MAX_N 100000
#define MAX_E 1600000
#define D     128
#define SCAN_BS 1024

// ---------------- static device scratch ----------------
__device__ int   g_cnt [MAX_N];
__device__ int   g_off [MAX_N + 1];
__device__ int   g_cur [MAX_N];
__device__ int   g_csr [MAX_E];
__device__ int   g_bsum[256];
__device__ float g_dinv[MAX_N];
__device__ float g_G[(size_t)MAX_N * D];
__device__ float g_H[(size_t)MAX_N * D];

// ---------------- degree histogram / dinv ----------------
__global__ void k_zero_cnt(int* cnt, int N) {
    int i = blockIdx.x * blockDim.x + threadIdx.x;
    if (i < N) cnt[i] = 0;
}

__global__ void k_hist(int* cnt, const int* __restrict__ dst, int E) {
    int e = blockIdx.x * blockDim.x + threadIdx.x;
    if (e < E) atomicAdd(&cnt[dst[e]], 1);
}

__global__ void k_dinv(const int* __restrict__ cnt, float* __restrict__ dinv,
                       int* __restrict__ off, int N, int E) {
    int i = blockIdx.x * blockDim.x + threadIdx.x;
    if (i < N) dinv[i] = rsqrtf((float)(cnt[i] + 1));   // +1 self loop
    if (i == 0) off[N] = E;
}

// ---------------- 3-pass exclusive scan of cnt -> off ----------------
__global__ void k_scan1(const int* __restrict__ cnt, int* __restrict__ off,
                        int* __restrict__ bsum, int N) {
    __shared__ int sm[SCAN_BS];
    int i = blockIdx.x * SCAN_BS + threadIdx.x;
    int v = (i < N) ? cnt[i] : 0;
    sm[threadIdx.x] = v;
    __syncthreads();
    #pragma unroll
    for (int s = 1; s < SCAN_BS; s <<= 1) {
        int t = (threadIdx.x >= s) ? sm[threadIdx.x - s] : 0;
        __syncthreads();
        sm[threadIdx.x] += t;
        __syncthreads();
    }
    if (i < N) off[i] = sm[threadIdx.x] - v;   // local exclusive
    if (threadIdx.x == SCAN_BS - 1) bsum[blockIdx.x] = sm[threadIdx.x];
}

__global__ void k_scan2(int* bsum, int nb) {
    __shared__ int sm[256];
    int i = threadIdx.x;
    int v = (i < nb) ? bsum[i] : 0;
    sm[i] = v;
    __syncthreads();
    #pragma unroll
    for (int s = 1; s < 256; s <<= 1) {
        int t = (i >= s) ? sm[i - s] : 0;
        __syncthreads();
        sm[i] += t;
        __syncthreads();
    }
    if (i < nb) bsum[i] = sm[i] - v;   // exclusive
}

__global__ void k_scan3(int* __restrict__ off, int* __restrict__ cur,
                        const int* __restrict__ bsum, int N) {
    int i = blockIdx.x * SCAN_BS + threadIdx.x;
    if (i < N) {
        int o = off[i] + bsum[blockIdx.x];
        off[i] = o;
        cur[i] = o;
    }
}

// ---------------- CSR fill ----------------
__global__ void k_fill(const int* __restrict__ src, const int* __restrict__ dst,
                       int* __restrict__ cur, int* __restrict__ csr, int E) {
    int e = blockIdx.x * blockDim.x + threadIdx.x;
    if (e < E) {
        int pos = atomicAdd(&cur[dst[e]], 1);
        csr[pos] = src[e];
    }
}

// ---------------- fused GEMM + row scale:  G = (X @ W) * dinv[row] ----------------
// BM=64 rows per CTA, k processed in float4 chunks: 12 LDS.128 per 128 FFMAs.
#define GEMM_BM 64
#define GEMM_SMEM ((GEMM_BM + 128) * 128 * 4)   // 32KB xs + 64KB ws

__global__ void __launch_bounds__(256)
k_gemm_scale(const float* __restrict__ X, const float* __restrict__ W,
             const float* __restrict__ dinv, float* __restrict__ G, int N) {
    extern __shared__ float sm[];
    float* xs = sm;                   // [BM][128]
    float* ws = sm + GEMM_BM * 128;   // [128][128]
    int tid  = threadIdx.x;
    int row0 = blockIdx.x * GEMM_BM;

    {   // stage W
        const float4* Wv = (const float4*)W;
        float4* wsv = (float4*)ws;
        for (int i = tid; i < 128 * 32; i += 256) wsv[i] = Wv[i];
    }
    {   // stage X tile
        float4* xsv = (float4*)xs;
        for (int i = tid; i < GEMM_BM * 32; i += 256) {
            int r = i >> 5, c = i & 31;
            int gr = row0 + r;
            float4 v = make_float4(0.f, 0.f, 0.f, 0.f);
            if (gr < N) v = ((const float4*)(X + (size_t)gr * D))[c];
            xsv[i] = v;
        }
    }
    __syncthreads();

    int tn = tid & 31;    // output col group (4 cols)
    int tm = tid >> 5;    // row group (8 rows)
    const float4* xsv = (const float4*)xs;
    const float4* wsv = (const float4*)ws;

    float4 acc[8];
    #pragma unroll
    for (int r = 0; r < 8; r++) acc[r] = make_float4(0.f, 0.f, 0.f, 0.f);

    #pragma unroll 4
    for (int k4 = 0; k4 < 32; k4++) {
        float4 b0 = wsv[(4 * k4 + 0) * 32 + tn];
        float4 b1 = wsv[(4 * k4 + 1) * 32 + tn];
        float4 b2 = wsv[(4 * k4 + 2) * 32 + tn];
        float4 b3 = wsv[(4 * k4 + 3) * 32 + tn];
        #pragma unroll
        for (int r = 0; r < 8; r++) {
            float4 a = xsv[(tm * 8 + r) * 32 + k4];
            acc[r].x = fmaf(a.x, b0.x, fmaf(a.y, b1.x, fmaf(a.z, b2.x, fmaf(a.w, b3.x, acc[r].x))));
            acc[r].y = fmaf(a.x, b0.y, fmaf(a.y, b1.y, fmaf(a.z, b2.y, fmaf(a.w, b3.y, acc[r].y))));
            acc[r].z = fmaf(a.x, b0.z, fmaf(a.y, b1.z, fmaf(a.z, b2.z, fmaf(a.w, b3.z, acc[r].z))));
            acc[r].w = fmaf(a.x, b0.w, fmaf(a.y, b1.w, fmaf(a.z, b2.w, fmaf(a.w, b3.w, acc[r].w))));
        }
    }

    #pragma unroll
    for (int r = 0; r < 8; r++) {
        int gr = row0 + tm * 8 + r;
        if (gr < N) {
            float dv = dinv[gr];
            float4 v = make_float4(acc[r].x * dv, acc[r].y * dv, acc[r].z * dv, acc[r].w * dv);
            ((float4*)(G + (size_t)gr * D))[tn] = v;
        }
    }
}

// ---------------- CSR gather conv:  H[i] = [relu](dinv[i]*(G[i] + sum G[src]) + b) ----------------
template <bool RELU>
__global__ void __launch_bounds__(256)
k_gather(const float* __restrict__ G, const float* __restrict__ dinv,
         const float* __restrict__ b, float* __restrict__ H,
         const int* __restrict__ off, const int* __restrict__ csr, int N) {
    int gtid = blockIdx.x * blockDim.x + threadIdx.x;
    int w    = gtid >> 5;
    int lane = gtid & 31;
    if (w >= N) return;

    const float4* Gv = (const float4*)G;
    float4 acc = Gv[(size_t)w * 32 + lane];          // self loop
    int e   = off[w];
    int end = off[w + 1];

    for (; e + 4 <= end; e += 4) {
        int s0 = csr[e], s1 = csr[e + 1], s2 = csr[e + 2], s3 = csr[e + 3];
        float4 v0 = Gv[(size_t)s0 * 32 + lane];
        float4 v1 = Gv[(size_t)s1 * 32 + lane];
        float4 v2 = Gv[(size_t)s2 * 32 + lane];
        float4 v3 = Gv[(size_t)s3 * 32 + lane];
        acc.x += (v0.x + v1.x) + (v2.x + v3.x);
        acc.y += (v0.y + v1.y) + (v2.y + v3.y);
        acc.z += (v0.z + v1.z) + (v2.z + v3.z);
        acc.w += (v0.w + v1.w) + (v2.w + v3.w);
    }
    for (; e < end; e++) {
        float4 v = Gv[(size_t)csr[e] * 32 + lane];
        acc.x += v.x; acc.y += v.y; acc.z += v.z; acc.w += v.w;
    }

    float  dv = dinv[w];
    float4 bb = ((const float4*)b)[lane];
    acc.x = fmaf(acc.x, dv, bb.x);
    acc.y = fmaf(acc.y, dv, bb.y);
    acc.z = fmaf(acc.z, dv, bb.z);
    acc.w = fmaf(acc.w, dv, bb.w);
    if (RELU) {
        acc.x = fmaxf(acc.x, 0.f); acc.y = fmaxf(acc.y, 0.f);
        acc.z = fmaxf(acc.z, 0.f); acc.w = fmaxf(acc.w, 0.f);
    }
    ((float4*)H)[(size_t)w * 32 + lane] = acc;
}

// ---------------- pair dot products (pos + neg in one launch) ----------------
__global__ void __launch_bounds__(256)
k_pairs(const float* __restrict__ H, const int* __restrict__ pos,
        const int* __restrict__ neg, float* __restrict__ out, int P) {
    int gtid = blockIdx.x * blockDim.x + threadIdx.x;
    int w    = gtid >> 5;
    int lane = gtid & 31;
    if (w >= 2 * P) return;
    const int* pr = (w < P) ? pos : neg;
    int idx = (w < P) ? w : (w - P);
    int u = pr[2 * idx];
    int v = pr[2 * idx + 1];
    float4 a = ((const float4*)(H + (size_t)u * D))[lane];
    float4 c = ((const float4*)(H + (size_t)v * D))[lane];
    float s = a.x * c.x + a.y * c.y + a.z * c.z + a.w * c.w;
    #pragma unroll
    for (int o = 16; o; o >>= 1) s += __shfl_xor_sync(0xFFFFFFFFu, s, o);
    if (lane == 0) out[w] = s;
}

// ---------------- launch ----------------
template <typename T>
static inline T* symaddr(const void* sym) {
    void* p = nullptr;
    cudaGetSymbolAddress(&p, sym);
    return (T*)p;
}

extern "C" void kernel_launch(void* const* d_in, const int* in_sizes, int n_in,
                              void* d_out, int out_size) {
    const float* x  = (const float*)d_in[0];
    const float* W1 = (const float*)d_in[1];
    const float* b1 = (const float*)d_in[2];
    const float* W2 = (const float*)d_in[3];
    const float* b2 = (const float*)d_in[4];
    const int* eidx = (const int*)d_in[5];
    const int* ppos = (const int*)d_in[6];
    const int* pneg = (const int*)d_in[7];
    float* out = (float*)d_out;

    const int N = in_sizes[0] / D;
    const int E = in_sizes[5] / 2;
    const int P = in_sizes[6] / 2;
    const int* src = eidx;
    const int* dst = eidx + E;

    int*   cnt  = symaddr<int>(g_cnt);
    int*   off  = symaddr<int>(g_off);
    int*   cur  = symaddr<int>(g_cur);
    int*   csr  = symaddr<int>(g_csr);
    int*   bsum = symaddr<int>(g_bsum);
    float* dinv = symaddr<float>(g_dinv);
    float* G    = symaddr<float>(g_G);
    float* H    = symaddr<float>(g_H);

    cudaFuncSetAttribute(k_gemm_scale, cudaFuncAttributeMaxDynamicSharedMemorySize, GEMM_SMEM);

    const int T = 256;
    int gridN     = (N + T - 1) / T;
    int gridE     = (E + T - 1) / T;
    int nbScan    = (N + SCAN_BS - 1) / SCAN_BS;
    int gridGemm  = (N + GEMM_BM - 1) / GEMM_BM;
    int gridGath  = (int)(((long long)N * 32 + T - 1) / T);
    int gridPairs = (int)(((long long)2 * P * 32 + T - 1) / T);

    // degree histogram + dinv + CSR
    k_zero_cnt<<<gridN, T>>>(cnt, N);
    k_hist    <<<gridE, T>>>(cnt, dst, E);
    k_dinv    <<<gridN, T>>>(cnt, dinv, off, N, E);
    k_scan1   <<<nbScan, SCAN_BS>>>(cnt, off, bsum, N);
    k_scan2   <<<1, 256>>>(bsum, nbScan);
    k_scan3   <<<nbScan, SCAN_BS>>>(off, cur, bsum, N);
    k_fill    <<<gridE, T>>>(src, dst, cur, csr, E);

    // layer 1
    k_gemm_scale  <<<gridGemm, T, GEMM_SMEM>>>(x, W1, dinv, G, N);
    k_gather<true><<<gridGath, T>>>(G, dinv, b1, H, off, csr, N);

    // layer 2
    k_gemm_scale   <<<gridGemm, T, GEMM_SMEM>>>(H, W2, dinv, G, N);
    k_gather<false><<<gridGath, T>>>(G, dinv, b2, H, off, csr, N);

    // link prediction
    k_pairs<<<gridPairs, T>>>(H, ppos, pneg, out, P);
}

// round 3
// speedup vs baseline: 1.5992x; 1.0305x over previous
#include <cuda_runtime.h>
#include <cuda_bf16.h>
#include <cstdint>

#define MAX_N 100000
#define MAX_E 1600000
#define D     128
#define SCAN_BS 1024

// ---------------- static device scratch ----------------
__device__ int   g_cnt [MAX_N];
__device__ int   g_off [MAX_N + 1];
__device__ int   g_cur [MAX_N];
__device__ int   g_csr [MAX_E];
__device__ int   g_bsum[256];
__device__ float g_dinv[MAX_N];
__device__ float g_G[(size_t)MAX_N * D];
__device__ float g_H[(size_t)MAX_N * D];

// ---------------- degree histogram ----------------
__global__ void k_hist(int* cnt, const int* __restrict__ dst, int E) {
    int e = blockIdx.x * blockDim.x + threadIdx.x;
    if (e < E) atomicAdd(&cnt[dst[e]], 1);
}

// ---------------- 3-pass exclusive scan of cnt -> off (+dinv fused) ----------------
__global__ void k_scan1(const int* __restrict__ cnt, int* __restrict__ off,
                        int* __restrict__ bsum, float* __restrict__ dinv, int N) {
    __shared__ int sm[SCAN_BS];
    int i = blockIdx.x * SCAN_BS + threadIdx.x;
    int v = (i < N) ? cnt[i] : 0;
    if (i < N) dinv[i] = rsqrtf((float)(v + 1));   // +1 self loop
    sm[threadIdx.x] = v;
    __syncthreads();
    #pragma unroll
    for (int s = 1; s < SCAN_BS; s <<= 1) {
        int t = (threadIdx.x >= s) ? sm[threadIdx.x - s] : 0;
        __syncthreads();
        sm[threadIdx.x] += t;
        __syncthreads();
    }
    if (i < N) off[i] = sm[threadIdx.x] - v;   // local exclusive
    if (threadIdx.x == SCAN_BS - 1) bsum[blockIdx.x] = sm[threadIdx.x];
}

__global__ void k_scan2(int* bsum, int nb) {
    __shared__ int sm[256];
    int i = threadIdx.x;
    int v = (i < nb) ? bsum[i] : 0;
    sm[i] = v;
    __syncthreads();
    #pragma unroll
    for (int s = 1; s < 256; s <<= 1) {
        int t = (i >= s) ? sm[i - s] : 0;
        __syncthreads();
        sm[i] += t;
        __syncthreads();
    }
    if (i < nb) bsum[i] = sm[i] - v;   // exclusive
}

__global__ void k_scan3(int* __restrict__ off, int* __restrict__ cur,
                        const int* __restrict__ bsum, int N, int E) {
    int i = blockIdx.x * SCAN_BS + threadIdx.x;
    if (i < N) {
        int o = off[i] + bsum[blockIdx.x];
        off[i] = o;
        cur[i] = o;
        if (i == N - 1) off[N] = E;
    }
}

// ---------------- CSR fill ----------------
__global__ void k_fill(const int* __restrict__ src, const int* __restrict__ dst,
                       int* __restrict__ cur, int* __restrict__ csr, int E) {
    int e = blockIdx.x * blockDim.x + threadIdx.x;
    if (e < E) {
        int pos = atomicAdd(&cur[dst[e]], 1);
        csr[pos] = src[e];
    }
}

// ---------------- GEMM:  G = X @ W  (no dinv — graph-independent) ----------------
#define GEMM_BM 64
#define GEMM_SMEM ((GEMM_BM + 128) * 128 * 4)   // 32KB xs + 64KB ws

__global__ void __launch_bounds__(256)
k_gemm(const float* __restrict__ X, const float* __restrict__ W,
       float* __restrict__ G, int N) {
    extern __shared__ float sm[];
    float* xs = sm;                   // [BM][128]
    float* ws = sm + GEMM_BM * 128;   // [128][128]
    int tid  = threadIdx.x;
    int row0 = blockIdx.x * GEMM_BM;

    {   // stage W
        const float4* Wv = (const float4*)W;
        float4* wsv = (float4*)ws;
        for (int i = tid; i < 128 * 32; i += 256) wsv[i] = Wv[i];
    }
    {   // stage X tile
        float4* xsv = (float4*)xs;
        for (int i = tid; i < GEMM_BM * 32; i += 256) {
            int r = i >> 5, c = i & 31;
            int gr = row0 + r;
            float4 v = make_float4(0.f, 0.f, 0.f, 0.f);
            if (gr < N) v = ((const float4*)(X + (size_t)gr * D))[c];
            xsv[i] = v;
        }
    }
    __syncthreads();

    int tn = tid & 31;
    int tm = tid >> 5;
    const float4* xsv = (const float4*)xs;
    const float4* wsv = (const float4*)ws;

    float4 acc[8];
    #pragma unroll
    for (int r = 0; r < 8; r++) acc[r] = make_float4(0.f, 0.f, 0.f, 0.f);

    #pragma unroll 4
    for (int k4 = 0; k4 < 32; k4++) {
        float4 b0 = wsv[(4 * k4 + 0) * 32 + tn];
        float4 b1 = wsv[(4 * k4 + 1) * 32 + tn];
        float4 b2 = wsv[(4 * k4 + 2) * 32 + tn];
        float4 b3 = wsv[(4 * k4 + 3) * 32 + tn];
        #pragma unroll
        for (int r = 0; r < 8; r++) {
            float4 a = xsv[(tm * 8 + r) * 32 + k4];
            acc[r].x = fmaf(a.x, b0.x, fmaf(a.y, b1.x, fmaf(a.z, b2.x, fmaf(a.w, b3.x, acc[r].x))));
            acc[r].y = fmaf(a.x, b0.y, fmaf(a.y, b1.y, fmaf(a.z, b2.y, fmaf(a.w, b3.y, acc[r].y))));
            acc[r].z = fmaf(a.x, b0.z, fmaf(a.y, b1.z, fmaf(a.z, b2.z, fmaf(a.w, b3.z, acc[r].z))));
            acc[r].w = fmaf(a.x, b0.w, fmaf(a.y, b1.w, fmaf(a.z, b2.w, fmaf(a.w, b3.w, acc[r].w))));
        }
    }

    #pragma unroll
    for (int r = 0; r < 8; r++) {
        int gr = row0 + tm * 8 + r;
        if (gr < N)
            ((float4*)(G + (size_t)gr * D))[tn] = acc[r];
    }
}

// ---------- CSR gather conv: H[i] = [relu](dinv[i]*(dinv[i]*G[i] + sum dinv[s]*G[s]) + b) ----------
template <bool RELU>
__global__ void __launch_bounds__(256)
k_gather(const float* __restrict__ G, const float* __restrict__ dinv,
         const float* __restrict__ b, float* __restrict__ H,
         const int* __restrict__ off, const int* __restrict__ csr, int N) {
    int gtid = blockIdx.x * blockDim.x + threadIdx.x;
    int w    = gtid >> 5;
    int lane = gtid & 31;
    if (w >= N) return;

    const float4* Gv = (const float4*)G;
    float dw = dinv[w];
    float4 self = Gv[(size_t)w * 32 + lane];
    float4 acc  = make_float4(self.x * dw, self.y * dw, self.z * dw, self.w * dw);
    int e   = off[w];
    int end = off[w + 1];

    for (; e + 4 <= end; e += 4) {
        int s0 = csr[e], s1 = csr[e + 1], s2 = csr[e + 2], s3 = csr[e + 3];
        float d0 = dinv[s0], d1 = dinv[s1], d2 = dinv[s2], d3 = dinv[s3];
        float4 v0 = Gv[(size_t)s0 * 32 + lane];
        float4 v1 = Gv[(size_t)s1 * 32 + lane];
        float4 v2 = Gv[(size_t)s2 * 32 + lane];
        float4 v3 = Gv[(size_t)s3 * 32 + lane];
        acc.x += (v0.x * d0 + v1.x * d1) + (v2.x * d2 + v3.x * d3);
        acc.y += (v0.y * d0 + v1.y * d1) + (v2.y * d2 + v3.y * d3);
        acc.z += (v0.z * d0 + v1.z * d1) + (v2.z * d2 + v3.z * d3);
        acc.w += (v0.w * d0 + v1.w * d1) + (v2.w * d2 + v3.w * d3);
    }
    for (; e < end; e++) {
        int s = csr[e];
        float ds = dinv[s];
        float4 v = Gv[(size_t)s * 32 + lane];
        acc.x = fmaf(v.x, ds, acc.x); acc.y = fmaf(v.y, ds, acc.y);
        acc.z = fmaf(v.z, ds, acc.z); acc.w = fmaf(v.w, ds, acc.w);
    }

    float4 bb = ((const float4*)b)[lane];
    acc.x = fmaf(acc.x, dw, bb.x);
    acc.y = fmaf(acc.y, dw, bb.y);
    acc.z = fmaf(acc.z, dw, bb.z);
    acc.w = fmaf(acc.w, dw, bb.w);
    if (RELU) {
        acc.x = fmaxf(acc.x, 0.f); acc.y = fmaxf(acc.y, 0.f);
        acc.z = fmaxf(acc.z, 0.f); acc.w = fmaxf(acc.w, 0.f);
    }
    ((float4*)H)[(size_t)w * 32 + lane] = acc;
}

// ---------------- pair dot products (pos + neg in one launch) ----------------
__global__ void __launch_bounds__(256)
k_pairs(const float* __restrict__ H, const int* __restrict__ pos,
        const int* __restrict__ neg, float* __restrict__ out, int P) {
    int gtid = blockIdx.x * blockDim.x + threadIdx.x;
    int w    = gtid >> 5;
    int lane = gtid & 31;
    if (w >= 2 * P) return;
    const int* pr = (w < P) ? pos : neg;
    int idx = (w < P) ? w : (w - P);
    int u = pr[2 * idx];
    int v = pr[2 * idx + 1];
    float4 a = ((const float4*)(H + (size_t)u * D))[lane];
    float4 c = ((const float4*)(H + (size_t)v * D))[lane];
    float s = a.x * c.x + a.y * c.y + a.z * c.z + a.w * c.w;
    #pragma unroll
    for (int o = 16; o; o >>= 1) s += __shfl_xor_sync(0xFFFFFFFFu, s, o);
    if (lane == 0) out[w] = s;
}

// ---------------- launch ----------------
template <typename T>
static inline T* symaddr(const void* sym) {
    void* p = nullptr;
    cudaGetSymbolAddress(&p, sym);
    return (T*)p;
}

extern "C" void kernel_launch(void* const* d_in, const int* in_sizes, int n_in,
                              void* d_out, int out_size) {
    const float* x  = (const float*)d_in[0];
    const float* W1 = (const float*)d_in[1];
    const float* b1 = (const float*)d_in[2];
    const float* W2 = (const float*)d_in[3];
    const float* b2 = (const float*)d_in[4];
    const int* eidx = (const int*)d_in[5];
    const int* ppos = (const int*)d_in[6];
    const int* pneg = (const int*)d_in[7];
    float* out = (float*)d_out;

    const int N = in_sizes[0] / D;
    const int E = in_sizes[5] / 2;
    const int P = in_sizes[6] / 2;
    const int* src = eidx;
    const int* dst = eidx + E;

    int*   cnt  = symaddr<int>(g_cnt);
    int*   off  = symaddr<int>(g_off);
    int*   cur  = symaddr<int>(g_cur);
    int*   csr  = symaddr<int>(g_csr);
    int*   bsum = symaddr<int>(g_bsum);
    float* dinv = symaddr<float>(g_dinv);
    float* G    = symaddr<float>(g_G);
    float* H    = symaddr<float>(g_H);

    // persistent side stream + fork/join events (created once; deterministic work)
    static cudaStream_t s_side = nullptr;
    static cudaEvent_t  ev_fork = nullptr, ev_join = nullptr;
    if (!s_side) {
        cudaStreamCreateWithFlags(&s_side, cudaStreamNonBlocking);
        cudaEventCreateWithFlags(&ev_fork, cudaEventDisableTiming);
        cudaEventCreateWithFlags(&ev_join, cudaEventDisableTiming);
    }

    cudaFuncSetAttribute(k_gemm, cudaFuncAttributeMaxDynamicSharedMemorySize, GEMM_SMEM);

    const int T = 256;
    int gridE     = (E + T - 1) / T;
    int nbScan    = (N + SCAN_BS - 1) / SCAN_BS;
    int gridGemm  = (N + GEMM_BM - 1) / GEMM_BM;
    int gridGath  = (int)(((long long)N * 32 + T - 1) / T);
    int gridPairs = (int)(((long long)2 * P * 32 + T - 1) / T);

    // fork: CSR build on side stream, concurrent with GEMM1 on main stream
    cudaEventRecord(ev_fork, 0);
    cudaStreamWaitEvent(s_side, ev_fork, 0);

    cudaMemsetAsync(cnt, 0, (size_t)N * sizeof(int), s_side);
    k_hist <<<gridE, T, 0, s_side>>>(cnt, dst, E);
    k_scan1<<<nbScan, SCAN_BS, 0, s_side>>>(cnt, off, bsum, dinv, N);
    k_scan2<<<1, 256, 0, s_side>>>(bsum, nbScan);
    k_scan3<<<nbScan, SCAN_BS, 0, s_side>>>(off, cur, bsum, N, E);
    k_fill <<<gridE, T, 0, s_side>>>(src, dst, cur, csr, E);
    cudaEventRecord(ev_join, s_side);

    // main stream: GEMM1 (graph-independent), then join before gather
    k_gemm<<<gridGemm, T, GEMM_SMEM>>>(x, W1, G, N);
    cudaStreamWaitEvent(0, ev_join, 0);

    k_gather<true><<<gridGath, T>>>(G, dinv, b1, H, off, csr, N);

    // layer 2
    k_gemm<<<gridGemm, T, GEMM_SMEM>>>(H, W2, G, N);
    k_gather<false><<<gridGath, T>>>(G, dinv, b2, H, off, csr, N);

    // link prediction
    k_pairs<<<gridPairs, T>>>(H, ppos, pneg, out, P);
}